// round 4
// baseline (speedup 1.0000x reference)
#include <cuda_runtime.h>

#define DD 256
#define NMAX 150000
#define NDMAX (NMAX * DD)
#define NNZMAX 6600000

typedef unsigned long long ull;

// ---------------- scratch (static device memory; no allocation) ----------------
__device__ float g_T[NDMAX];       // GEMM output / SpMM input
__device__ float g_X[NDMAX];       // x state
__device__ float g_B0[NDMAX];      // b ping
__device__ float g_B1[NDMAX];      // b pong
__device__ int   g_cnt[NMAX];      // per-row degree
__device__ int   g_rowptr[NMAX + 1];
__device__ int   g_cursor[NMAX];
__device__ int   g_ci[NNZMAX];     // CSR col indices
__device__ float g_cv[NNZMAX];     // CSR values
__device__ int   g_bsum[1024];     // scan block sums

// ---------------- CSR build ----------------
__global__ void zero_cnt_kernel(int n) {
    int i = blockIdx.x * blockDim.x + threadIdx.x;
    if (i < n) g_cnt[i] = 0;
}

__global__ void hist_kernel(const int* __restrict__ rows, int nnz) {
    int i = blockIdx.x * blockDim.x + threadIdx.x;
    if (i < nnz) atomicAdd(&g_cnt[rows[i]], 1);
}

__global__ void scan1_kernel(int n) {
    __shared__ int s[256];
    int t = threadIdx.x;
    int i = blockIdx.x * 256 + t;
    int v = (i < n) ? g_cnt[i] : 0;
    s[t] = v;
    __syncthreads();
#pragma unroll
    for (int off = 1; off < 256; off <<= 1) {
        int tv = (t >= off) ? s[t - off] : 0;
        __syncthreads();
        s[t] += tv;
        __syncthreads();
    }
    if (i < n) g_rowptr[i] = s[t] - v;          // exclusive within block
    if (t == 255) g_bsum[blockIdx.x] = s[255];  // block total
}

__global__ void scan2_kernel(int nb) {
    __shared__ int s[1024];
    int t = threadIdx.x;
    int v = (t < nb) ? g_bsum[t] : 0;
    s[t] = v;
    __syncthreads();
#pragma unroll
    for (int off = 1; off < 1024; off <<= 1) {
        int tv = (t >= off) ? s[t - off] : 0;
        __syncthreads();
        s[t] += tv;
        __syncthreads();
    }
    if (t < nb) g_bsum[t] = s[t] - v;           // exclusive block offsets
}

__global__ void scan3_kernel(int n, int nnz) {
    int i = blockIdx.x * 256 + threadIdx.x;
    if (i < n) {
        int rp = g_rowptr[i] + g_bsum[blockIdx.x];
        g_rowptr[i] = rp;
        g_cursor[i] = rp;
        if (i == 0) g_rowptr[n] = nnz;
    }
}

__global__ void scatter_kernel(const int* __restrict__ rows,
                               const int* __restrict__ cols,
                               const float* __restrict__ vals, int nnz) {
    int i = blockIdx.x * blockDim.x + threadIdx.x;
    if (i < nnz) {
        int r = rows[i];
        int p = atomicAdd(&g_cursor[r], 1);
        g_ci[p] = cols[i];
        g_cv[p] = vals[i];
    }
}

// ---------------- SpMM + row L2-normalize + result accumulate (fused) ----------------
// one block per row, 256 threads = one column each; dual accumulators for FMA ILP
__global__ void spmm_norm_kernel(const float* __restrict__ T, float* __restrict__ X,
                                 float* __restrict__ R, const float* __restrict__ Rinit,
                                 float rsc) {
    int r = blockIdx.x;
    int d = threadIdx.x;
    int s = g_rowptr[r], e = g_rowptr[r + 1];

    __shared__ int   scol[128];
    __shared__ float sval[128];
    __shared__ float sred[8];
    __shared__ float sinv;

    float acc0 = 0.f, acc1 = 0.f;
    for (int j0 = s; j0 < e; j0 += 128) {
        int cnt = min(128, e - j0);
        if (d < cnt) { scol[d] = g_ci[j0 + d]; sval[d] = g_cv[j0 + d]; }
        __syncthreads();
        int j = 0;
        for (; j + 4 <= cnt; j += 4) {
            int c0 = scol[j] * DD, c1 = scol[j + 1] * DD;
            int c2 = scol[j + 2] * DD, c3 = scol[j + 3] * DD;
            float v0 = sval[j], v1 = sval[j + 1], v2 = sval[j + 2], v3 = sval[j + 3];
            float t0 = __ldg(&T[c0 + d]);
            float t1 = __ldg(&T[c1 + d]);
            float t2 = __ldg(&T[c2 + d]);
            float t3 = __ldg(&T[c3 + d]);
            acc0 = fmaf(v0, t0, acc0);
            acc1 = fmaf(v1, t1, acc1);
            acc0 = fmaf(v2, t2, acc0);
            acc1 = fmaf(v3, t3, acc1);
        }
        for (; j < cnt; j++) acc0 = fmaf(sval[j], __ldg(&T[scol[j] * DD + d]), acc0);
        __syncthreads();
    }
    float acc = acc0 + acc1;

    // block reduce ||row||^2
    float ss = acc * acc;
#pragma unroll
    for (int o = 16; o > 0; o >>= 1) ss += __shfl_xor_sync(0xffffffffu, ss, o);
    if ((d & 31) == 0) sred[d >> 5] = ss;
    __syncthreads();
    if (d == 0) {
        float t2 = 0.f;
#pragma unroll
        for (int w = 0; w < 8; w++) t2 += sred[w];
        sinv = 1.0f / fmaxf(sqrtf(t2), 1e-12f);
    }
    __syncthreads();
    float xv = acc * sinv;
    int o = r * DD + d;
    X[o] = xv;
    float base = Rinit ? Rinit[o] : R[o];
    R[o] = base + rsc * xv;
}

// ---------------- SGEMM: C[m,n] = sum_k (A[+A2])[m,k] * W[n,k], f32x2 inner loop ----------------
// BM=128, BN=128, BK=16, 256 threads, 8x8 micro-tile (8 rows x 4 f32x2 pairs)
// Register-prefetch pipeline: next tile's GMEM loads issued before current tile's compute.
template <bool ADD2, bool EPI>
__global__ void __launch_bounds__(256, 2)
gemm_kernel(const float* __restrict__ A, const float* __restrict__ A2,
            const float* __restrict__ W, float* __restrict__ C,
            float* __restrict__ E, const float* __restrict__ Einit,
            float esc, int M) {
    __shared__ float As[16][128];   // [k][m]
    __shared__ float Bs[16][128];   // [k][n]

    const int t = threadIdx.x;
    const int tx = t & 15, ty = t >> 4;
    const int bm = blockIdx.x * 128, bn = blockIdx.y * 128;

    // per-thread load coordinates (2 load slots covering 512 float4s per tile)
    int lrow[2], lc4[2], lgm[2];
#pragma unroll
    for (int l = 0; l < 2; l++) {
        int idx = t + l * 256;
        lrow[l] = idx >> 2;
        lc4[l]  = (idx & 3) << 2;
        lgm[l]  = bm + lrow[l];
    }

    ull acc[8][4];
#pragma unroll
    for (int i = 0; i < 8; i++)
#pragma unroll
        for (int j = 0; j < 4; j++) acc[i][j] = 0ull;

    float4 va[2], vb[2];

    // prefetch tile 0
#pragma unroll
    for (int l = 0; l < 2; l++) {
        float4 v = make_float4(0.f, 0.f, 0.f, 0.f);
        if (lgm[l] < M) {
            v = *reinterpret_cast<const float4*>(&A[lgm[l] * DD + lc4[l]]);
            if (ADD2) {
                float4 w2 = *reinterpret_cast<const float4*>(&A2[lgm[l] * DD + lc4[l]]);
                v.x += w2.x; v.y += w2.y; v.z += w2.z; v.w += w2.w;
            }
        }
        va[l] = v;
        vb[l] = *reinterpret_cast<const float4*>(&W[(bn + lrow[l]) * DD + lc4[l]]);
    }

    for (int kt = 0; kt < DD; kt += 16) {
        // commit prefetched tile to smem
#pragma unroll
        for (int l = 0; l < 2; l++) {
            As[lc4[l] + 0][lrow[l]] = va[l].x; As[lc4[l] + 1][lrow[l]] = va[l].y;
            As[lc4[l] + 2][lrow[l]] = va[l].z; As[lc4[l] + 3][lrow[l]] = va[l].w;
            Bs[lc4[l] + 0][lrow[l]] = vb[l].x; Bs[lc4[l] + 1][lrow[l]] = vb[l].y;
            Bs[lc4[l] + 2][lrow[l]] = vb[l].z; Bs[lc4[l] + 3][lrow[l]] = vb[l].w;
        }
        __syncthreads();

        // prefetch next tile into registers (overlaps with compute below)
        int ktn = kt + 16;
        if (ktn < DD) {
#pragma unroll
            for (int l = 0; l < 2; l++) {
                float4 v = make_float4(0.f, 0.f, 0.f, 0.f);
                if (lgm[l] < M) {
                    v = *reinterpret_cast<const float4*>(&A[lgm[l] * DD + ktn + lc4[l]]);
                    if (ADD2) {
                        float4 w2 = *reinterpret_cast<const float4*>(&A2[lgm[l] * DD + ktn + lc4[l]]);
                        v.x += w2.x; v.y += w2.y; v.z += w2.z; v.w += w2.w;
                    }
                }
                va[l] = v;
                vb[l] = *reinterpret_cast<const float4*>(&W[(bn + lrow[l]) * DD + ktn + lc4[l]]);
            }
        }

#pragma unroll
        for (int k = 0; k < 16; k++) {
            float4 a0 = *reinterpret_cast<const float4*>(&As[k][ty * 8]);
            float4 a1 = *reinterpret_cast<const float4*>(&As[k][ty * 8 + 4]);
            float4 b0 = *reinterpret_cast<const float4*>(&Bs[k][tx * 8]);
            float4 b1 = *reinterpret_cast<const float4*>(&Bs[k][tx * 8 + 4]);
            ull bp[4];
            bp[0] = reinterpret_cast<const ull*>(&b0)[0];
            bp[1] = reinterpret_cast<const ull*>(&b0)[1];
            bp[2] = reinterpret_cast<const ull*>(&b1)[0];
            bp[3] = reinterpret_cast<const ull*>(&b1)[1];
            float am[8] = {a0.x, a0.y, a0.z, a0.w, a1.x, a1.y, a1.z, a1.w};
#pragma unroll
            for (int mi = 0; mi < 8; mi++) {
                ull ap;
                asm("mov.b64 %0, {%1, %1};" : "=l"(ap) : "f"(am[mi]));
#pragma unroll
                for (int nj = 0; nj < 4; nj++)
                    asm("fma.rn.f32x2 %0, %1, %2, %0;"
                        : "+l"(acc[mi][nj])
                        : "l"(ap), "l"(bp[nj]));
            }
        }
        __syncthreads();
    }

#pragma unroll
    for (int mi = 0; mi < 8; mi++) {
        int gm = bm + ty * 8 + mi;
        if (gm >= M) continue;
        float out[8];
#pragma unroll
        for (int nj = 0; nj < 4; nj++) {
            float2 p = *reinterpret_cast<float2*>(&acc[mi][nj]);
            out[nj * 2] = p.x;
            out[nj * 2 + 1] = p.y;
        }
        int base = gm * DD + bn + tx * 8;
        *reinterpret_cast<float4*>(&C[base]) = make_float4(out[0], out[1], out[2], out[3]);
        *reinterpret_cast<float4*>(&C[base + 4]) = make_float4(out[4], out[5], out[6], out[7]);
        if (EPI) {
            float4 e0, e1;
            if (Einit) {
                e0 = *reinterpret_cast<const float4*>(&Einit[base]);
                e1 = *reinterpret_cast<const float4*>(&Einit[base + 4]);
            } else {
                e0 = *reinterpret_cast<float4*>(&E[base]);
                e1 = *reinterpret_cast<float4*>(&E[base + 4]);
            }
            e0.x += esc * out[0]; e0.y += esc * out[1];
            e0.z += esc * out[2]; e0.w += esc * out[3];
            e1.x += esc * out[4]; e1.y += esc * out[5];
            e1.z += esc * out[6]; e1.w += esc * out[7];
            *reinterpret_cast<float4*>(&E[base]) = e0;
            *reinterpret_cast<float4*>(&E[base + 4]) = e1;
        }
    }
}

// ---------------- launch ----------------
extern "C" void kernel_launch(void* const* d_in, const int* in_sizes, int n_in,
                              void* d_out, int out_size) {
    const float* in_embs  = (const float*)d_in[0];
    const float* beh      = (const float*)d_in[1];
    const float* node_ws  = (const float*)d_in[2];   // (3,256,256)
    const float* rel_ws   = (const float*)d_in[3];   // (3,256,256)
    const float* vals     = (const float*)d_in[4];
    const int*   rows     = (const int*)d_in[5];
    const int*   cols     = (const int*)d_in[6];

    int nnz = in_sizes[4];
    int M   = in_sizes[0] / DD;

    float* R  = (float*)d_out;               // result
    float* Bh = R + (size_t)M * DD;          // behaviors

    float *T, *X, *B0, *B1;
    cudaGetSymbolAddress((void**)&T,  g_T);
    cudaGetSymbolAddress((void**)&X,  g_X);
    cudaGetSymbolAddress((void**)&B0, g_B0);
    cudaGetSymbolAddress((void**)&B1, g_B1);

    // ---- CSR build (per call; graph-capturable) ----
    int nbRows = (M + 255) / 256;
    int nbE    = (nnz + 255) / 256;
    zero_cnt_kernel<<<nbRows, 256>>>(M);
    hist_kernel<<<nbE, 256>>>(rows, nnz);
    scan1_kernel<<<nbRows, 256>>>(M);
    scan2_kernel<<<1, 1024>>>(nbRows);
    scan3_kernel<<<nbRows, 256>>>(M, nnz);
    scatter_kernel<<<nbE, 256>>>(rows, cols, vals, nnz);

    dim3 gg((M + 127) / 128, 2);

    // ---- layer 0 ----
    gemm_kernel<true,  false><<<gg, 256>>>(in_embs, beh, node_ws, T, nullptr, nullptr, 0.f, M);
    spmm_norm_kernel<<<M, 256>>>(T, X, R, in_embs, 1.0f);
    gemm_kernel<false, true ><<<gg, 256>>>(beh, nullptr, rel_ws, B0, Bh, beh, 1.0f, M);

    // ---- layer 1 ----
    gemm_kernel<true,  false><<<gg, 256>>>(X, B0, node_ws + 65536, T, nullptr, nullptr, 0.f, M);
    spmm_norm_kernel<<<M, 256>>>(T, X, R, nullptr, 0.5f);
    gemm_kernel<false, true ><<<gg, 256>>>(B0, nullptr, rel_ws + 65536, B1, Bh, nullptr, 0.5f, M);

    // ---- layer 2 ----
    gemm_kernel<true,  false><<<gg, 256>>>(X, B1, node_ws + 131072, T, nullptr, nullptr, 0.f, M);
    spmm_norm_kernel<<<M, 256>>>(T, X, R, nullptr, 1.0f / 3.0f);
    gemm_kernel<false, true ><<<gg, 256>>>(B1, nullptr, rel_ws + 131072, B0, Bh, nullptr, 1.0f / 3.0f, M);
}

// round 9
// speedup vs baseline: 1.0365x; 1.0365x over previous
#include <cuda_runtime.h>

#define DD 256
#define NMAX 150000
#define NDMAX (NMAX * DD)
#define NNZMAX 6600000

typedef unsigned long long ull;

// ---------------- scratch (static device memory; no allocation) ----------------
__device__ float g_T[NDMAX];       // GEMM output / SpMM input
__device__ float g_X[NDMAX];       // x state
__device__ float g_B0[NDMAX];      // b after layer 0
__device__ float g_B1[NDMAX];      // b after layer 1
__device__ float g_B2[NDMAX];      // b after layer 2 (avoids WAR with nodeGEMM1 reading B0)
__device__ int   g_cnt[NMAX];      // per-row degree
__device__ int   g_rowptr[NMAX + 1];
__device__ int   g_cursor[NMAX];
__device__ int   g_ci[NNZMAX];     // CSR col indices
__device__ float g_cv[NNZMAX];     // CSR values
__device__ int   g_bsum[1024];     // scan block sums

// ---------------- CSR build ----------------
__global__ void zero_cnt_kernel(int n) {
    int i = blockIdx.x * blockDim.x + threadIdx.x;
    if (i < n) g_cnt[i] = 0;
}

__global__ void hist_kernel(const int* __restrict__ rows, int nnz) {
    int i = blockIdx.x * blockDim.x + threadIdx.x;
    if (i < nnz) atomicAdd(&g_cnt[rows[i]], 1);
}

__global__ void scan1_kernel(int n) {
    __shared__ int s[256];
    int t = threadIdx.x;
    int i = blockIdx.x * 256 + t;
    int v = (i < n) ? g_cnt[i] : 0;
    s[t] = v;
    __syncthreads();
#pragma unroll
    for (int off = 1; off < 256; off <<= 1) {
        int tv = (t >= off) ? s[t - off] : 0;
        __syncthreads();
        s[t] += tv;
        __syncthreads();
    }
    if (i < n) g_rowptr[i] = s[t] - v;          // exclusive within block
    if (t == 255) g_bsum[blockIdx.x] = s[255];  // block total
}

__global__ void scan2_kernel(int nb) {
    __shared__ int s[1024];
    int t = threadIdx.x;
    int v = (t < nb) ? g_bsum[t] : 0;
    s[t] = v;
    __syncthreads();
#pragma unroll
    for (int off = 1; off < 1024; off <<= 1) {
        int tv = (t >= off) ? s[t - off] : 0;
        __syncthreads();
        s[t] += tv;
        __syncthreads();
    }
    if (t < nb) g_bsum[t] = s[t] - v;           // exclusive block offsets
}

__global__ void scan3_kernel(int n, int nnz) {
    int i = blockIdx.x * 256 + threadIdx.x;
    if (i < n) {
        int rp = g_rowptr[i] + g_bsum[blockIdx.x];
        g_rowptr[i] = rp;
        g_cursor[i] = rp;
        if (i == 0) g_rowptr[n] = nnz;
    }
}

__global__ void scatter_kernel(const int* __restrict__ rows,
                               const int* __restrict__ cols,
                               const float* __restrict__ vals, int nnz) {
    int i = blockIdx.x * blockDim.x + threadIdx.x;
    if (i < nnz) {
        int r = rows[i];
        int p = atomicAdd(&g_cursor[r], 1);
        g_ci[p] = cols[i];
        g_cv[p] = vals[i];
    }
}

// ---------------- SpMM + row L2-normalize + result accumulate (fused) ----------------
// one block per row, 256 threads = one column each; dual accumulators for FMA ILP
__global__ void spmm_norm_kernel(const float* __restrict__ T, float* __restrict__ X,
                                 float* __restrict__ R, const float* __restrict__ Rinit,
                                 float rsc) {
    int r = blockIdx.x;
    int d = threadIdx.x;
    int s = g_rowptr[r], e = g_rowptr[r + 1];

    __shared__ int   scol[128];
    __shared__ float sval[128];
    __shared__ float sred[8];
    __shared__ float sinv;

    float acc0 = 0.f, acc1 = 0.f;
    for (int j0 = s; j0 < e; j0 += 128) {
        int cnt = min(128, e - j0);
        if (d < cnt) { scol[d] = g_ci[j0 + d]; sval[d] = g_cv[j0 + d]; }
        __syncthreads();
        int j = 0;
        for (; j + 4 <= cnt; j += 4) {
            int c0 = scol[j] * DD, c1 = scol[j + 1] * DD;
            int c2 = scol[j + 2] * DD, c3 = scol[j + 3] * DD;
            float v0 = sval[j], v1 = sval[j + 1], v2 = sval[j + 2], v3 = sval[j + 3];
            float t0 = __ldg(&T[c0 + d]);
            float t1 = __ldg(&T[c1 + d]);
            float t2 = __ldg(&T[c2 + d]);
            float t3 = __ldg(&T[c3 + d]);
            acc0 = fmaf(v0, t0, acc0);
            acc1 = fmaf(v1, t1, acc1);
            acc0 = fmaf(v2, t2, acc0);
            acc1 = fmaf(v3, t3, acc1);
        }
        for (; j < cnt; j++) acc0 = fmaf(sval[j], __ldg(&T[scol[j] * DD + d]), acc0);
        __syncthreads();
    }
    float acc = acc0 + acc1;

    // block reduce ||row||^2
    float ss = acc * acc;
#pragma unroll
    for (int o = 16; o > 0; o >>= 1) ss += __shfl_xor_sync(0xffffffffu, ss, o);
    if ((d & 31) == 0) sred[d >> 5] = ss;
    __syncthreads();
    if (d == 0) {
        float t2 = 0.f;
#pragma unroll
        for (int w = 0; w < 8; w++) t2 += sred[w];
        sinv = 1.0f / fmaxf(sqrtf(t2), 1e-12f);
    }
    __syncthreads();
    float xv = acc * sinv;
    int o = r * DD + d;
    X[o] = xv;
    float base = Rinit ? Rinit[o] : R[o];
    R[o] = base + rsc * xv;
}

// ---------------- SGEMM: C[m,n] = sum_k (A[+A2])[m,k] * W[n,k], f32x2 inner loop ----------------
// BM=128, BN=128, BK=16, 256 threads, 8x8 micro-tile (8 rows x 4 f32x2 pairs)
// Register-prefetch pipeline: next tile's GMEM loads issued before current tile's compute.
template <bool ADD2, bool EPI>
__global__ void __launch_bounds__(256, 2)
gemm_kernel(const float* __restrict__ A, const float* __restrict__ A2,
            const float* __restrict__ W, float* __restrict__ C,
            float* __restrict__ E, const float* __restrict__ Einit,
            float esc, int M) {
    __shared__ float As[16][128];   // [k][m]
    __shared__ float Bs[16][128];   // [k][n]

    const int t = threadIdx.x;
    const int tx = t & 15, ty = t >> 4;
    const int bm = blockIdx.x * 128, bn = blockIdx.y * 128;

    int lrow[2], lc4[2], lgm[2];
#pragma unroll
    for (int l = 0; l < 2; l++) {
        int idx = t + l * 256;
        lrow[l] = idx >> 2;
        lc4[l]  = (idx & 3) << 2;
        lgm[l]  = bm + lrow[l];
    }

    ull acc[8][4];
#pragma unroll
    for (int i = 0; i < 8; i++)
#pragma unroll
        for (int j = 0; j < 4; j++) acc[i][j] = 0ull;

    float4 va[2], vb[2];

    // prefetch tile 0
#pragma unroll
    for (int l = 0; l < 2; l++) {
        float4 v = make_float4(0.f, 0.f, 0.f, 0.f);
        if (lgm[l] < M) {
            v = *reinterpret_cast<const float4*>(&A[lgm[l] * DD + lc4[l]]);
            if (ADD2) {
                float4 w2 = *reinterpret_cast<const float4*>(&A2[lgm[l] * DD + lc4[l]]);
                v.x += w2.x; v.y += w2.y; v.z += w2.z; v.w += w2.w;
            }
        }
        va[l] = v;
        vb[l] = *reinterpret_cast<const float4*>(&W[(bn + lrow[l]) * DD + lc4[l]]);
    }

    for (int kt = 0; kt < DD; kt += 16) {
#pragma unroll
        for (int l = 0; l < 2; l++) {
            As[lc4[l] + 0][lrow[l]] = va[l].x; As[lc4[l] + 1][lrow[l]] = va[l].y;
            As[lc4[l] + 2][lrow[l]] = va[l].z; As[lc4[l] + 3][lrow[l]] = va[l].w;
            Bs[lc4[l] + 0][lrow[l]] = vb[l].x; Bs[lc4[l] + 1][lrow[l]] = vb[l].y;
            Bs[lc4[l] + 2][lrow[l]] = vb[l].z; Bs[lc4[l] + 3][lrow[l]] = vb[l].w;
        }
        __syncthreads();

        int ktn = kt + 16;
        if (ktn < DD) {
#pragma unroll
            for (int l = 0; l < 2; l++) {
                float4 v = make_float4(0.f, 0.f, 0.f, 0.f);
                if (lgm[l] < M) {
                    v = *reinterpret_cast<const float4*>(&A[lgm[l] * DD + ktn + lc4[l]]);
                    if (ADD2) {
                        float4 w2 = *reinterpret_cast<const float4*>(&A2[lgm[l] * DD + ktn + lc4[l]]);
                        v.x += w2.x; v.y += w2.y; v.z += w2.z; v.w += w2.w;
                    }
                }
                va[l] = v;
                vb[l] = *reinterpret_cast<const float4*>(&W[(bn + lrow[l]) * DD + ktn + lc4[l]]);
            }
        }

#pragma unroll
        for (int k = 0; k < 16; k++) {
            float4 a0 = *reinterpret_cast<const float4*>(&As[k][ty * 8]);
            float4 a1 = *reinterpret_cast<const float4*>(&As[k][ty * 8 + 4]);
            float4 b0 = *reinterpret_cast<const float4*>(&Bs[k][tx * 8]);
            float4 b1 = *reinterpret_cast<const float4*>(&Bs[k][tx * 8 + 4]);
            ull bp[4];
            bp[0] = reinterpret_cast<const ull*>(&b0)[0];
            bp[1] = reinterpret_cast<const ull*>(&b0)[1];
            bp[2] = reinterpret_cast<const ull*>(&b1)[0];
            bp[3] = reinterpret_cast<const ull*>(&b1)[1];
            float am[8] = {a0.x, a0.y, a0.z, a0.w, a1.x, a1.y, a1.z, a1.w};
#pragma unroll
            for (int mi = 0; mi < 8; mi++) {
                ull ap;
                asm("mov.b64 %0, {%1, %1};" : "=l"(ap) : "f"(am[mi]));
#pragma unroll
                for (int nj = 0; nj < 4; nj++)
                    asm("fma.rn.f32x2 %0, %1, %2, %0;"
                        : "+l"(acc[mi][nj])
                        : "l"(ap), "l"(bp[nj]));
            }
        }
        __syncthreads();
    }

#pragma unroll
    for (int mi = 0; mi < 8; mi++) {
        int gm = bm + ty * 8 + mi;
        if (gm >= M) continue;
        float out[8];
#pragma unroll
        for (int nj = 0; nj < 4; nj++) {
            float2 p = *reinterpret_cast<float2*>(&acc[mi][nj]);
            out[nj * 2] = p.x;
            out[nj * 2 + 1] = p.y;
        }
        int base = gm * DD + bn + tx * 8;
        *reinterpret_cast<float4*>(&C[base]) = make_float4(out[0], out[1], out[2], out[3]);
        *reinterpret_cast<float4*>(&C[base + 4]) = make_float4(out[4], out[5], out[6], out[7]);
        if (EPI) {
            float4 e0, e1;
            if (Einit) {
                e0 = *reinterpret_cast<const float4*>(&Einit[base]);
                e1 = *reinterpret_cast<const float4*>(&Einit[base + 4]);
            } else {
                e0 = *reinterpret_cast<float4*>(&E[base]);
                e1 = *reinterpret_cast<float4*>(&E[base + 4]);
            }
            e0.x += esc * out[0]; e0.y += esc * out[1];
            e0.z += esc * out[2]; e0.w += esc * out[3];
            e1.x += esc * out[4]; e1.y += esc * out[5];
            e1.z += esc * out[6]; e1.w += esc * out[7];
            *reinterpret_cast<float4*>(&E[base]) = e0;
            *reinterpret_cast<float4*>(&E[base + 4]) = e1;
        }
    }
}

// ---------------- stream/event lazy init (host resources only; no device mem) ----------------
static cudaStream_t g_s2 = nullptr;
static cudaEvent_t  g_evFork, g_evCsr, g_evB0, g_evB1, g_evJoin;

// ---------------- launch ----------------
extern "C" void kernel_launch(void* const* d_in, const int* in_sizes, int n_in,
                              void* d_out, int out_size) {
    const float* in_embs  = (const float*)d_in[0];
    const float* beh      = (const float*)d_in[1];
    const float* node_ws  = (const float*)d_in[2];   // (3,256,256)
    const float* rel_ws   = (const float*)d_in[3];   // (3,256,256)
    const float* vals     = (const float*)d_in[4];
    const int*   rows     = (const int*)d_in[5];
    const int*   cols     = (const int*)d_in[6];

    int nnz = in_sizes[4];
    int M   = in_sizes[0] / DD;

    float* R  = (float*)d_out;               // result
    float* Bh = R + (size_t)M * DD;          // behaviors

    float *T, *X, *B0, *B1, *B2;
    cudaGetSymbolAddress((void**)&T,  g_T);
    cudaGetSymbolAddress((void**)&X,  g_X);
    cudaGetSymbolAddress((void**)&B0, g_B0);
    cudaGetSymbolAddress((void**)&B1, g_B1);
    cudaGetSymbolAddress((void**)&B2, g_B2);

    if (!g_s2) {   // one-time host-side resource init (first call is uncaptured)
        cudaStreamCreateWithFlags(&g_s2, cudaStreamNonBlocking);
        cudaEventCreateWithFlags(&g_evFork, cudaEventDisableTiming);
        cudaEventCreateWithFlags(&g_evCsr,  cudaEventDisableTiming);
        cudaEventCreateWithFlags(&g_evB0,   cudaEventDisableTiming);
        cudaEventCreateWithFlags(&g_evB1,   cudaEventDisableTiming);
        cudaEventCreateWithFlags(&g_evJoin, cudaEventDisableTiming);
    }

    int nbRows = (M + 255) / 256;
    int nbE    = (nnz + 255) / 256;
    dim3 gg((M + 127) / 128, 2);

    // fork side stream off the main (capture) stream
    cudaEventRecord(g_evFork, 0);
    cudaStreamWaitEvent(g_s2, g_evFork, 0);

    // ---- s2: CSR build, then the independent rel-GEMM chain ----
    zero_cnt_kernel<<<nbRows, 256, 0, g_s2>>>(M);
    hist_kernel<<<nbE, 256, 0, g_s2>>>(rows, nnz);
    scan1_kernel<<<nbRows, 256, 0, g_s2>>>(M);
    scan2_kernel<<<1, 1024, 0, g_s2>>>(nbRows);
    scan3_kernel<<<nbRows, 256, 0, g_s2>>>(M, nnz);
    scatter_kernel<<<nbE, 256, 0, g_s2>>>(rows, cols, vals, nnz);
    cudaEventRecord(g_evCsr, g_s2);

    gemm_kernel<false, true><<<gg, 256, 0, g_s2>>>(beh, nullptr, rel_ws,          B0, Bh, beh,     1.0f,        M);
    cudaEventRecord(g_evB0, g_s2);
    gemm_kernel<false, true><<<gg, 256, 0, g_s2>>>(B0,  nullptr, rel_ws + 65536,  B1, Bh, nullptr, 0.5f,        M);
    cudaEventRecord(g_evB1, g_s2);
    gemm_kernel<false, true><<<gg, 256, 0, g_s2>>>(B1,  nullptr, rel_ws + 131072, B2, Bh, nullptr, 1.0f / 3.0f, M);
    cudaEventRecord(g_evJoin, g_s2);

    // ---- main stream: node-GEMM -> SpMM chain ----
    gemm_kernel<true, false><<<gg, 256>>>(in_embs, beh, node_ws, T, nullptr, nullptr, 0.f, M);
    cudaStreamWaitEvent(0, g_evCsr, 0);
    spmm_norm_kernel<<<M, 256>>>(T, X, R, in_embs, 1.0f);

    cudaStreamWaitEvent(0, g_evB0, 0);
    gemm_kernel<true, false><<<gg, 256>>>(X, B0, node_ws + 65536, T, nullptr, nullptr, 0.f, M);
    spmm_norm_kernel<<<M, 256>>>(T, X, R, nullptr, 0.5f);

    cudaStreamWaitEvent(0, g_evB1, 0);
    gemm_kernel<true, false><<<gg, 256>>>(X, B1, node_ws + 131072, T, nullptr, nullptr, 0.f, M);
    spmm_norm_kernel<<<M, 256>>>(T, X, R, nullptr, 1.0f / 3.0f);

    // rejoin fork before capture ends
    cudaStreamWaitEvent(0, g_evJoin, 0);
}

// round 12
// speedup vs baseline: 1.2284x; 1.1852x over previous
#include <cuda_runtime.h>

#define DD 256
#define NMAX 150000
#define NDMAX (NMAX * DD)
#define NNZMAX 6600000

typedef unsigned long long ull;

// ---------------- scratch (static device memory; no allocation) ----------------
__device__ float g_T[NDMAX];       // GEMM output / SpMM input
__device__ float g_X[NDMAX];       // x state
__device__ float g_B0[NDMAX];      // b after layer 0
__device__ float g_B1[NDMAX];      // b after layer 1
__device__ float g_B2[NDMAX];      // b after layer 2
__device__ int   g_cnt[NMAX];      // per-row degree
__device__ int   g_rowptr[NMAX + 1];
__device__ int   g_cursor[NMAX];
__device__ int   g_ci[NNZMAX];     // CSR col indices
__device__ float g_cv[NNZMAX];     // CSR values
__device__ int   g_bsum[1024];     // scan block sums

// ---------------- CSR build ----------------
__global__ void zero_cnt_kernel(int n) {
    int i = blockIdx.x * blockDim.x + threadIdx.x;
    if (i < n) g_cnt[i] = 0;
}

__global__ void hist_kernel(const int* __restrict__ rows, int nnz) {
    int i = blockIdx.x * blockDim.x + threadIdx.x;
    if (i < nnz) atomicAdd(&g_cnt[rows[i]], 1);
}

__global__ void scan1_kernel(int n) {
    __shared__ int s[256];
    int t = threadIdx.x;
    int i = blockIdx.x * 256 + t;
    int v = (i < n) ? g_cnt[i] : 0;
    s[t] = v;
    __syncthreads();
#pragma unroll
    for (int off = 1; off < 256; off <<= 1) {
        int tv = (t >= off) ? s[t - off] : 0;
        __syncthreads();
        s[t] += tv;
        __syncthreads();
    }
    if (i < n) g_rowptr[i] = s[t] - v;
    if (t == 255) g_bsum[blockIdx.x] = s[255];
}

__global__ void scan2_kernel(int nb) {
    __shared__ int s[1024];
    int t = threadIdx.x;
    int v = (t < nb) ? g_bsum[t] : 0;
    s[t] = v;
    __syncthreads();
#pragma unroll
    for (int off = 1; off < 1024; off <<= 1) {
        int tv = (t >= off) ? s[t - off] : 0;
        __syncthreads();
        s[t] += tv;
        __syncthreads();
    }
    if (t < nb) g_bsum[t] = s[t] - v;
}

__global__ void scan3_kernel(int n, int nnz) {
    int i = blockIdx.x * 256 + threadIdx.x;
    if (i < n) {
        int rp = g_rowptr[i] + g_bsum[blockIdx.x];
        g_rowptr[i] = rp;
        g_cursor[i] = rp;
        if (i == 0) g_rowptr[n] = nnz;
    }
}

__global__ void scatter_kernel(const int* __restrict__ rows,
                               const int* __restrict__ cols,
                               const float* __restrict__ vals, int nnz) {
    int i = blockIdx.x * blockDim.x + threadIdx.x;
    if (i < nnz) {
        int r = rows[i];
        int p = atomicAdd(&g_cursor[r], 1);
        g_ci[p] = cols[i];
        g_cv[p] = vals[i];
    }
}

// ---------------- SpMM + row L2-normalize + result accumulate (fused, float4) ----------------
// one block per row, 64 threads = one float4 (4 cols) each; 4-way neighbor unroll for MLP
__global__ void __launch_bounds__(64)
spmm_norm_kernel(const float4* __restrict__ T4, float4* __restrict__ X4,
                 float4* __restrict__ R4, const float4* __restrict__ Rinit4,
                 float rsc) {
    int r = blockIdx.x;
    int d = threadIdx.x;          // 0..63, covers cols 4d..4d+3
    int s = g_rowptr[r], e = g_rowptr[r + 1];

    __shared__ int   scol[64];
    __shared__ float sval[64];
    __shared__ float sred[2];
    __shared__ float sinv;

    float4 a0 = make_float4(0.f, 0.f, 0.f, 0.f);
    float4 a1 = make_float4(0.f, 0.f, 0.f, 0.f);

    for (int j0 = s; j0 < e; j0 += 64) {
        int cnt = min(64, e - j0);
        if (d < cnt) { scol[d] = g_ci[j0 + d]; sval[d] = g_cv[j0 + d]; }
        __syncthreads();
        int j = 0;
        for (; j + 4 <= cnt; j += 4) {
            int c0 = scol[j] * 64, c1 = scol[j + 1] * 64;
            int c2 = scol[j + 2] * 64, c3 = scol[j + 3] * 64;
            float v0 = sval[j], v1 = sval[j + 1], v2 = sval[j + 2], v3 = sval[j + 3];
            float4 t0 = __ldg(&T4[c0 + d]);
            float4 t1 = __ldg(&T4[c1 + d]);
            float4 t2 = __ldg(&T4[c2 + d]);
            float4 t3 = __ldg(&T4[c3 + d]);
            a0.x = fmaf(v0, t0.x, a0.x); a0.y = fmaf(v0, t0.y, a0.y);
            a0.z = fmaf(v0, t0.z, a0.z); a0.w = fmaf(v0, t0.w, a0.w);
            a1.x = fmaf(v1, t1.x, a1.x); a1.y = fmaf(v1, t1.y, a1.y);
            a1.z = fmaf(v1, t1.z, a1.z); a1.w = fmaf(v1, t1.w, a1.w);
            a0.x = fmaf(v2, t2.x, a0.x); a0.y = fmaf(v2, t2.y, a0.y);
            a0.z = fmaf(v2, t2.z, a0.z); a0.w = fmaf(v2, t2.w, a0.w);
            a1.x = fmaf(v3, t3.x, a1.x); a1.y = fmaf(v3, t3.y, a1.y);
            a1.z = fmaf(v3, t3.z, a1.z); a1.w = fmaf(v3, t3.w, a1.w);
        }
        for (; j < cnt; j++) {
            int c = scol[j] * 64;
            float v = sval[j];
            float4 t = __ldg(&T4[c + d]);
            a0.x = fmaf(v, t.x, a0.x); a0.y = fmaf(v, t.y, a0.y);
            a0.z = fmaf(v, t.z, a0.z); a0.w = fmaf(v, t.w, a0.w);
        }
        __syncthreads();
    }
    float4 acc = make_float4(a0.x + a1.x, a0.y + a1.y, a0.z + a1.z, a0.w + a1.w);

    // block reduce ||row||^2 over 64 threads (2 warps)
    float ss = acc.x * acc.x + acc.y * acc.y + acc.z * acc.z + acc.w * acc.w;
#pragma unroll
    for (int o = 16; o > 0; o >>= 1) ss += __shfl_xor_sync(0xffffffffu, ss, o);
    if ((d & 31) == 0) sred[d >> 5] = ss;
    __syncthreads();
    if (d == 0) sinv = 1.0f / fmaxf(sqrtf(sred[0] + sred[1]), 1e-12f);
    __syncthreads();
    float iv = sinv;
    float4 xv = make_float4(acc.x * iv, acc.y * iv, acc.z * iv, acc.w * iv);
    int o = r * 64 + d;
    X4[o] = xv;
    float4 base = Rinit4 ? __ldg(&Rinit4[o]) : R4[o];
    base.x += rsc * xv.x; base.y += rsc * xv.y;
    base.z += rsc * xv.z; base.w += rsc * xv.w;
    R4[o] = base;
}

// ---------------- SGEMM: C[m,n] = sum_k (A[+A2])[m,k] * W[n,k], f32x2 inner loop ----------------
// BM=128, BN=128, BK=16, 256 threads, 8x8 micro-tile; register-prefetch pipeline.
template <bool ADD2, bool EPI>
__global__ void __launch_bounds__(256, 2)
gemm_kernel(const float* __restrict__ A, const float* __restrict__ A2,
            const float* __restrict__ W, float* __restrict__ C,
            float* __restrict__ E, const float* __restrict__ Einit,
            float esc, int M) {
    __shared__ float As[16][128];
    __shared__ float Bs[16][128];

    const int t = threadIdx.x;
    const int tx = t & 15, ty = t >> 4;
    const int bm = blockIdx.x * 128, bn = blockIdx.y * 128;

    int lrow[2], lc4[2], lgm[2];
#pragma unroll
    for (int l = 0; l < 2; l++) {
        int idx = t + l * 256;
        lrow[l] = idx >> 2;
        lc4[l]  = (idx & 3) << 2;
        lgm[l]  = bm + lrow[l];
    }

    ull acc[8][4];
#pragma unroll
    for (int i = 0; i < 8; i++)
#pragma unroll
        for (int j = 0; j < 4; j++) acc[i][j] = 0ull;

    float4 va[2], vb[2];

#pragma unroll
    for (int l = 0; l < 2; l++) {
        float4 v = make_float4(0.f, 0.f, 0.f, 0.f);
        if (lgm[l] < M) {
            v = *reinterpret_cast<const float4*>(&A[lgm[l] * DD + lc4[l]]);
            if (ADD2) {
                float4 w2 = *reinterpret_cast<const float4*>(&A2[lgm[l] * DD + lc4[l]]);
                v.x += w2.x; v.y += w2.y; v.z += w2.z; v.w += w2.w;
            }
        }
        va[l] = v;
        vb[l] = *reinterpret_cast<const float4*>(&W[(bn + lrow[l]) * DD + lc4[l]]);
    }

    for (int kt = 0; kt < DD; kt += 16) {
#pragma unroll
        for (int l = 0; l < 2; l++) {
            As[lc4[l] + 0][lrow[l]] = va[l].x; As[lc4[l] + 1][lrow[l]] = va[l].y;
            As[lc4[l] + 2][lrow[l]] = va[l].z; As[lc4[l] + 3][lrow[l]] = va[l].w;
            Bs[lc4[l] + 0][lrow[l]] = vb[l].x; Bs[lc4[l] + 1][lrow[l]] = vb[l].y;
            Bs[lc4[l] + 2][lrow[l]] = vb[l].z; Bs[lc4[l] + 3][lrow[l]] = vb[l].w;
        }
        __syncthreads();

        int ktn = kt + 16;
        if (ktn < DD) {
#pragma unroll
            for (int l = 0; l < 2; l++) {
                float4 v = make_float4(0.f, 0.f, 0.f, 0.f);
                if (lgm[l] < M) {
                    v = *reinterpret_cast<const float4*>(&A[lgm[l] * DD + ktn + lc4[l]]);
                    if (ADD2) {
                        float4 w2 = *reinterpret_cast<const float4*>(&A2[lgm[l] * DD + ktn + lc4[l]]);
                        v.x += w2.x; v.y += w2.y; v.z += w2.z; v.w += w2.w;
                    }
                }
                va[l] = v;
                vb[l] = *reinterpret_cast<const float4*>(&W[(bn + lrow[l]) * DD + ktn + lc4[l]]);
            }
        }

#pragma unroll
        for (int k = 0; k < 16; k++) {
            float4 a0 = *reinterpret_cast<const float4*>(&As[k][ty * 8]);
            float4 a1 = *reinterpret_cast<const float4*>(&As[k][ty * 8 + 4]);
            float4 b0 = *reinterpret_cast<const float4*>(&Bs[k][tx * 8]);
            float4 b1 = *reinterpret_cast<const float4*>(&Bs[k][tx * 8 + 4]);
            ull bp[4];
            bp[0] = reinterpret_cast<const ull*>(&b0)[0];
            bp[1] = reinterpret_cast<const ull*>(&b0)[1];
            bp[2] = reinterpret_cast<const ull*>(&b1)[0];
            bp[3] = reinterpret_cast<const ull*>(&b1)[1];
            float am[8] = {a0.x, a0.y, a0.z, a0.w, a1.x, a1.y, a1.z, a1.w};
#pragma unroll
            for (int mi = 0; mi < 8; mi++) {
                ull ap;
                asm("mov.b64 %0, {%1, %1};" : "=l"(ap) : "f"(am[mi]));
#pragma unroll
                for (int nj = 0; nj < 4; nj++)
                    asm("fma.rn.f32x2 %0, %1, %2, %0;"
                        : "+l"(acc[mi][nj])
                        : "l"(ap), "l"(bp[nj]));
            }
        }
        __syncthreads();
    }

#pragma unroll
    for (int mi = 0; mi < 8; mi++) {
        int gm = bm + ty * 8 + mi;
        if (gm >= M) continue;
        float out[8];
#pragma unroll
        for (int nj = 0; nj < 4; nj++) {
            float2 p = *reinterpret_cast<float2*>(&acc[mi][nj]);
            out[nj * 2] = p.x;
            out[nj * 2 + 1] = p.y;
        }
        int base = gm * DD + bn + tx * 8;
        *reinterpret_cast<float4*>(&C[base]) = make_float4(out[0], out[1], out[2], out[3]);
        *reinterpret_cast<float4*>(&C[base + 4]) = make_float4(out[4], out[5], out[6], out[7]);
        if (EPI) {
            float4 e0, e1;
            if (Einit) {
                e0 = *reinterpret_cast<const float4*>(&Einit[base]);
                e1 = *reinterpret_cast<const float4*>(&Einit[base + 4]);
            } else {
                e0 = *reinterpret_cast<float4*>(&E[base]);
                e1 = *reinterpret_cast<float4*>(&E[base + 4]);
            }
            e0.x += esc * out[0]; e0.y += esc * out[1];
            e0.z += esc * out[2]; e0.w += esc * out[3];
            e1.x += esc * out[4]; e1.y += esc * out[5];
            e1.z += esc * out[6]; e1.w += esc * out[7];
            *reinterpret_cast<float4*>(&E[base]) = e0;
            *reinterpret_cast<float4*>(&E[base + 4]) = e1;
        }
    }
}

// ---------------- stream/event lazy init (host resources only; no device mem) ----------------
static cudaStream_t g_s2 = nullptr;
static cudaEvent_t  g_evFork, g_evCsr, g_evB0, g_evB1, g_evJoin;

// ---------------- launch ----------------
extern "C" void kernel_launch(void* const* d_in, const int* in_sizes, int n_in,
                              void* d_out, int out_size) {
    const float* in_embs  = (const float*)d_in[0];
    const float* beh      = (const float*)d_in[1];
    const float* node_ws  = (const float*)d_in[2];
    const float* rel_ws   = (const float*)d_in[3];
    const float* vals     = (const float*)d_in[4];
    const int*   rows     = (const int*)d_in[5];
    const int*   cols     = (const int*)d_in[6];

    int nnz = in_sizes[4];
    int M   = in_sizes[0] / DD;

    float* R  = (float*)d_out;
    float* Bh = R + (size_t)M * DD;

    float *T, *X, *B0, *B1, *B2;
    cudaGetSymbolAddress((void**)&T,  g_T);
    cudaGetSymbolAddress((void**)&X,  g_X);
    cudaGetSymbolAddress((void**)&B0, g_B0);
    cudaGetSymbolAddress((void**)&B1, g_B1);
    cudaGetSymbolAddress((void**)&B2, g_B2);

    if (!g_s2) {
        cudaStreamCreateWithFlags(&g_s2, cudaStreamNonBlocking);
        cudaEventCreateWithFlags(&g_evFork, cudaEventDisableTiming);
        cudaEventCreateWithFlags(&g_evCsr,  cudaEventDisableTiming);
        cudaEventCreateWithFlags(&g_evB0,   cudaEventDisableTiming);
        cudaEventCreateWithFlags(&g_evB1,   cudaEventDisableTiming);
        cudaEventCreateWithFlags(&g_evJoin, cudaEventDisableTiming);
    }

    int nbRows = (M + 255) / 256;
    int nbE    = (nnz + 255) / 256;
    dim3 gg((M + 127) / 128, 2);

    cudaEventRecord(g_evFork, 0);
    cudaStreamWaitEvent(g_s2, g_evFork, 0);

    // ---- s2: CSR build, then the independent rel-GEMM chain ----
    zero_cnt_kernel<<<nbRows, 256, 0, g_s2>>>(M);
    hist_kernel<<<nbE, 256, 0, g_s2>>>(rows, nnz);
    scan1_kernel<<<nbRows, 256, 0, g_s2>>>(M);
    scan2_kernel<<<1, 1024, 0, g_s2>>>(nbRows);
    scan3_kernel<<<nbRows, 256, 0, g_s2>>>(M, nnz);
    scatter_kernel<<<nbE, 256, 0, g_s2>>>(rows, cols, vals, nnz);
    cudaEventRecord(g_evCsr, g_s2);

    gemm_kernel<false, true><<<gg, 256, 0, g_s2>>>(beh, nullptr, rel_ws,          B0, Bh, beh,     1.0f,        M);
    cudaEventRecord(g_evB0, g_s2);
    gemm_kernel<false, true><<<gg, 256, 0, g_s2>>>(B0,  nullptr, rel_ws + 65536,  B1, Bh, nullptr, 0.5f,        M);
    cudaEventRecord(g_evB1, g_s2);
    gemm_kernel<false, true><<<gg, 256, 0, g_s2>>>(B1,  nullptr, rel_ws + 131072, B2, Bh, nullptr, 1.0f / 3.0f, M);
    cudaEventRecord(g_evJoin, g_s2);

    // ---- main stream: node-GEMM -> SpMM chain ----
    gemm_kernel<true, false><<<gg, 256>>>(in_embs, beh, node_ws, T, nullptr, nullptr, 0.f, M);
    cudaStreamWaitEvent(0, g_evCsr, 0);
    spmm_norm_kernel<<<M, 64>>>((const float4*)T, (float4*)X, (float4*)R, (const float4*)in_embs, 1.0f);

    cudaStreamWaitEvent(0, g_evB0, 0);
    gemm_kernel<true, false><<<gg, 256>>>(X, B0, node_ws + 65536, T, nullptr, nullptr, 0.f, M);
    spmm_norm_kernel<<<M, 64>>>((const float4*)T, (float4*)X, (float4*)R, nullptr, 0.5f);

    cudaStreamWaitEvent(0, g_evB1, 0);
    gemm_kernel<true, false><<<gg, 256>>>(X, B1, node_ws + 131072, T, nullptr, nullptr, 0.f, M);
    spmm_norm_kernel<<<M, 64>>>((const float4*)T, (float4*)X, (float4*)R, nullptr, 1.0f / 3.0f);

    cudaStreamWaitEvent(0, g_evJoin, 0);
}